// round 11
// baseline (speedup 1.0000x reference)
#include <cuda_runtime.h>
#include <math.h>

// ---------------------------------------------------------------------------
// SimplifiedIFEBranch — R11: de-fused into 4 kernels (per-phase ncu visibility,
// unconstrained grids, no software barriers). FC = W-tile smem stage + FFMA2,
// K-split partials into bias-preinit accumulators via atomicAdd.
// ---------------------------------------------------------------------------

#define NBINS 32

__device__ __forceinline__ float c_LO() { return (float)(-3.2 - (6.4 / 256.0) / 2.0); }
__device__ __forceinline__ float c_HI() { return (float)( 3.2 - (6.4 / 256.0) / 2.0); }
__device__ __forceinline__ float c_BW() {
    return (float)(((3.2 - (6.4 / 256.0) / 2.0) - (-3.2 - (6.4 / 256.0) / 2.0)) / 32.0);
}

// Scratch (__device__ globals; no allocation allowed)
__device__ float g_histP[3072 * 32];   // pair-packed: [(k/2)][b][2]
__device__ float g_x1T[1024 * 32];     // [n][b] accum, bias-preinit
__device__ float g_x2T[512 * 32];

// ---- packed f32x2 helpers ---------------------------------------------------
__device__ __forceinline__ unsigned long long pack2(float x, float y) {
    unsigned long long r;
    asm("mov.b64 %0, {%1, %2};" : "=l"(r) : "f"(x), "f"(y));
    return r;
}
__device__ __forceinline__ void ffma2(unsigned long long& d,
                                      unsigned long long a, unsigned long long b) {
    asm("fma.rn.f32x2 %0, %1, %2, %0;" : "+l"(d) : "l"(a), "l"(b));
}
__device__ __forceinline__ float unpack_sum(unsigned long long p) {
    float lo, hi;
    asm("mov.b64 {%0, %1}, %2;" : "=f"(lo), "=f"(hi) : "l"(p));
    return lo + hi;
}

// ---- histogram helper ---------------------------------------------------------
__device__ __forceinline__ void hist_add(float* h, float Iu, float Iv, float w) {
    const float LO = c_LO(), HI = c_HI(), BW = c_BW();
    if (Iu >= LO && Iu <= HI && Iv >= LO && Iv <= HI) {
        int iu = (int)floorf((Iu - LO) / BW);
        int iv = (int)floorf((Iv - LO) / BW);
        iu = min(max(iu, 0), NBINS - 1);
        iv = min(max(iv, 0), NBINS - 1);
        atomicAdd(&h[iu * NBINS + iv], w);
    }
}

// ---- Kernel 1: histogram (CTAs 0..31) + bias pre-init (CTAs 32..127) -----------
__global__ __launch_bounds__(512) void hist_kernel(
    const float* __restrict__ img,
    const float* __restrict__ b1, const float* __restrict__ b2,
    float* __restrict__ histP, float* __restrict__ x1T, float* __restrict__ x2T) {

    __shared__ float sh[3 * 1024];
    __shared__ float ssum[3];
    const int cta = blockIdx.x;
    const int tid = threadIdx.x;

    if (cta >= 32) {
        // 96 CTAs x 512 = 49152 threads -> exactly 32768 + 16384 elements
        const int idx = (cta - 32) * 512 + tid;
        if (idx < 32768) __stcg(&x1T[idx], __ldcg(b1 + (idx >> 5)));
        else             { int j = idx - 32768; __stcg(&x2T[j], __ldcg(b2 + (j >> 5))); }
        return;
    }

    const int b = cta;
    // batched pixel loads first
    const float* base = img + (size_t)b * 3 * 262144;
    const int p0 = tid, p1 = tid + 512;
    const int off0 = ((p0 >> 5) * 16) * 512 + ((p0 & 31) * 16);
    const int off1 = ((p1 >> 5) * 16) * 512 + ((p1 & 31) * 16);
    float r0 = __ldcg(base + off0);
    float g0 = __ldcg(base + 262144 + off0);
    float l0 = __ldcg(base + 524288 + off0);
    float r1 = __ldcg(base + off1);
    float g1 = __ldcg(base + 262144 + off1);
    float l1 = __ldcg(base + 524288 + off1);

    #pragma unroll
    for (int i = tid; i < 3072; i += 512) sh[i] = 0.0f;
    if (tid < 3) ssum[tid] = 0.0f;
    __syncthreads();

    if (r0 > 0.0f && g0 > 0.0f && l0 > 0.0f) {
        float w  = sqrtf(r0 * r0 + g0 * g0 + l0 * l0);
        float lr = logf(r0), lg = logf(g0), lb = logf(l0);
        hist_add(&sh[0],    lr - lb, lr - lg, w);
        hist_add(&sh[1024], lg - lb, lg - lr, w);
        hist_add(&sh[2048], lb - lg, lb - lr, w);
    }
    if (r1 > 0.0f && g1 > 0.0f && l1 > 0.0f) {
        float w  = sqrtf(r1 * r1 + g1 * g1 + l1 * l1);
        float lr = logf(r1), lg = logf(g1), lb = logf(l1);
        hist_add(&sh[0],    lr - lb, lr - lg, w);
        hist_add(&sh[1024], lg - lb, lg - lr, w);
        hist_add(&sh[2048], lb - lg, lb - lr, w);
    }
    __syncthreads();

    #pragma unroll
    for (int c = 0; c < 3; ++c) {
        float s = sh[c * 1024 + tid] + sh[c * 1024 + tid + 512];
        #pragma unroll
        for (int o = 16; o > 0; o >>= 1) s += __shfl_down_sync(0xffffffffu, s, o);
        if ((tid & 31) == 0) atomicAdd(&ssum[c], s);
    }
    __syncthreads();

    // pair-packed write: histP[(k/2)*64 + b*2 + (k&1)]
    #pragma unroll
    for (int i = tid; i < 1024; i += 512) {
        #pragma unroll
        for (int c = 0; c < 3; ++c) {
            const int k = c * 1024 + i;
            float v = sqrtf(sh[c * 1024 + i] / ssum[c]);
            __stcg(&histP[(k >> 1) * 64 + b * 2 + (k & 1)], v);
        }
    }
}

// ---- FC kernel: one CTA = NROWS neurons x KS of K ---------------------------------
// Grid.x = (Ntotal/NROWS) * (KTOT/KS); nb = blockIdx.x % (Ntotal/NROWS).
// 16 warps = KG k-groups x NG n-groups; NT neurons/warp; lane = batch.
template <int KTOT, int KS, int NB, int NROWS, int NT, int NG, int KG, int HALVES,
          bool RELU_IN, bool PACKED_A, bool ATOMIC_OUT>
__global__ __launch_bounds__(512) void fc_kernel(
    const float* __restrict__ AT, const float* __restrict__ Wg,
    const float* __restrict__ bias, float* __restrict__ dest, int ldo) {

    extern __shared__ float buf[];           // W tile [NROWS][KS] + scratch
    constexpr int CH = KS / KG;
    constexpr int NK = CH / HALVES;
    const int nb   = blockIdx.x % NB;
    const int kb   = blockIdx.x / NB;
    const int n0   = nb * NROWS;
    const int K0   = kb * KS;
    const int tid  = threadIdx.x;
    const int lane = tid & 31;
    const int w    = tid >> 5;
    const int kg   = w / NG;
    const int ng   = w % NG;

    // stage W tile (coalesced float4, each element once per kb-split)
    {
        constexpr int F4 = NROWS * KS / 4;
        constexpr int RF = KS / 4;
        #pragma unroll
        for (int f = tid; f < F4; f += 512) {
            const int row = f / RF, col = f - row * RF;
            reinterpret_cast<float4*>(buf)[f] = __ldcg(
                reinterpret_cast<const float4*>(Wg + (size_t)(n0 + row) * KTOT + K0 + col * 4));
        }
    }
    __syncthreads();

    unsigned long long acc2[NT];
    #pragma unroll
    for (int t = 0; t < NT; ++t) acc2[t] = 0ull;

    const int kbase = K0 + kg * CH;
    const float* wrow0 = buf + (size_t)(ng * NT) * KS + kg * CH;

    #pragma unroll
    for (int h = 0; h < HALVES; ++h) {
        const int kh = kbase + h * NK;
        unsigned long long ap[NK / 2];
        if (PACKED_A) {
            const unsigned long long* src =
                reinterpret_cast<const unsigned long long*>(AT) + (size_t)(kh >> 1) * 32 + lane;
            #pragma unroll
            for (int j = 0; j < NK / 2; ++j) ap[j] = __ldcg(src + (size_t)j * 32);
        } else {
            #pragma unroll
            for (int j = 0; j < NK / 2; ++j) {
                float a0 = __ldcg(AT + (size_t)(kh + 2 * j) * 32 + lane);
                float a1 = __ldcg(AT + (size_t)(kh + 2 * j + 1) * 32 + lane);
                if (RELU_IN) { a0 = fmaxf(a0, 0.f); a1 = fmaxf(a1, 0.f); }
                ap[j] = pack2(a0, a1);
            }
        }
        #pragma unroll
        for (int j2 = 0; j2 < NK / 4; ++j2) {
            #pragma unroll
            for (int t = 0; t < NT; ++t) {
                ulonglong2 wv = *reinterpret_cast<const ulonglong2*>(
                    wrow0 + (size_t)t * KS + h * NK + 4 * j2);
                ffma2(acc2[t], wv.x, ap[2 * j2]);
                ffma2(acc2[t], wv.y, ap[2 * j2 + 1]);
            }
        }
    }
    __syncthreads();                         // W reads done; reuse buf

    #pragma unroll
    for (int t = 0; t < NT; ++t)
        buf[(w * NT + t) * 32 + lane] = unpack_sum(acc2[t]);
    __syncthreads();

    for (int n = w; n < NROWS; n += 16) {
        const int nng = n / NT, tt = n % NT;
        float s = 0.0f;
        #pragma unroll
        for (int kk = 0; kk < KG; ++kk)
            s += buf[((kk * NG + nng) * NT + tt) * 32 + lane];
        if (ATOMIC_OUT) {
            atomicAdd(&dest[(size_t)(n0 + n) * 32 + lane], s);
        } else {
            s += __ldcg(bias + n0 + n);
            s = fmaxf(s, 0.0f);
            dest[(size_t)lane * ldo + n0 + n] = s;
        }
    }
}

extern "C" void kernel_launch(void* const* d_in, const int* in_sizes, int n_in,
                              void* d_out, int out_size) {
    const float* inp = (const float*)d_in[0];
    const float* W1  = (const float*)d_in[1];
    const float* b1  = (const float*)d_in[2];
    const float* W2  = (const float*)d_in[3];
    const float* b2  = (const float*)d_in[4];
    const float* W3  = (const float*)d_in[5];
    const float* b3  = (const float*)d_in[6];
    float* out = (float*)d_out;

    float* histP; cudaGetSymbolAddress((void**)&histP, g_histP);
    float* x1T;   cudaGetSymbolAddress((void**)&x1T,   g_x1T);
    float* x2T;   cudaGetSymbolAddress((void**)&x2T,   g_x2T);

    // K1: histogram + bias pre-init
    hist_kernel<<<128, 512>>>(inp, b1, b2, histP, x1T, x2T);

    // K2: fc1 — 1024 x 3072, NB=32 (32 n) x kb=8 (384 K) = 256 CTAs, W tile 48 KB
    {
        constexpr int SM = 32 * 384 * 4;
        cudaFuncSetAttribute((const void*)fc_kernel<3072, 384, 32, 32, 16, 2, 8, 2, false, true, true>,
                             cudaFuncAttributeMaxDynamicSharedMemorySize, SM);
        fc_kernel<3072, 384, 32, 32, 16, 2, 8, 2, false, true, true>
            <<<256, 512, SM>>>(histP, W1, nullptr, x1T, 0);
    }
    // K3: fc2 — 512 x 1024, NB=32 (16 n) x kb=4 (256 K) = 128 CTAs, W tile 16 KB
    {
        constexpr int SM = 16 * 256 * 4;
        fc_kernel<1024, 256, 32, 16, 8, 2, 8, 1, true, false, true>
            <<<128, 512, SM>>>(x1T, W2, nullptr, x2T, 0);
    }
    // K4: fc3 — 256 x 512, NB=128 (2 n), full K = 128 CTAs, W tile 4 KB
    {
        constexpr int SM = 2 * 512 * 4;
        fc_kernel<512, 512, 128, 2, 2, 1, 16, 1, true, false, false>
            <<<128, 512, SM>>>(x2T, W3, b3, out, 256);
    }
}